// round 5
// baseline (speedup 1.0000x reference)
#include <cuda_runtime.h>
#include <cstdint>
#include <cstddef>

#define NN 16384
#define NE 8192
#define DF 64

// scratch (device-global; no allocations allowed)
__device__ float g_dv[NN];
__device__ float g_de[NE];
__device__ float g_X1[NN * DF];
__device__ float g_Y[NE * DF];

// ---------------- helpers ----------------
__device__ __forceinline__ uint32_t smem_u32(const void* p) {
    return (uint32_t)__cvta_generic_to_shared(p);
}
__device__ __forceinline__ void cp16(uint32_t s, const void* g) {
    asm volatile("cp.async.cg.shared.global [%0], [%1], 16;" :: "r"(s), "l"(g));
}
__device__ __forceinline__ void cp_commit() {
    asm volatile("cp.async.commit_group;" ::: "memory");
}
__device__ __forceinline__ void mma_tf32(float* c, const uint32_t* a, const uint32_t* b) {
    asm volatile(
        "mma.sync.aligned.m16n8k8.row.col.f32.tf32.tf32.f32 "
        "{%0,%1,%2,%3}, {%4,%5,%6,%7}, {%8,%9}, {%0,%1,%2,%3};\n"
        : "+f"(c[0]), "+f"(c[1]), "+f"(c[2]), "+f"(c[3])
        : "r"(a[0]), "r"(a[1]), "r"(a[2]), "r"(a[3]), "r"(b[0]), "r"(b[1]));
}
// round-to-nearest tf32 (result usable directly as mma operand; value = f32 with
// low mantissa bits cleared, so float(hi) is exact for the residual subtract)
__device__ __forceinline__ uint32_t tf32_rn(float x) {
    uint32_t r;
    asm("cvt.rna.tf32.f32 %0, %1;" : "=r"(r) : "f"(x));
    return r;
}
__device__ __forceinline__ void tf32_split(float x, uint32_t& hi, uint32_t& lo) {
    hi = tf32_rn(x);
    lo = tf32_rn(x - __uint_as_float(hi));
}

// ---------------- kernel 1: d_v, X1 = d_v*X, d_e partials, zero Y ----------------
__global__ __launch_bounds__(256) void k_deg(const float* __restrict__ H,
                                             const float* __restrict__ X) {
    const int t = threadIdx.x;
    const int r0 = blockIdx.x * 128;
    const int wid = t >> 5, lane = t & 31;
    __shared__ float s_wpart[128][8];
    __shared__ float s_dv[128];

    float4 acc_de[8];
#pragma unroll
    for (int i = 0; i < 8; ++i) acc_de[i] = make_float4(0.f, 0.f, 0.f, 0.f);

    for (int r = 0; r < 128; ++r) {
        const float4* row = reinterpret_cast<const float4*>(H + (size_t)(r0 + r) * NE);
        float rs = 0.f;
#pragma unroll
        for (int i = 0; i < 8; ++i) {
            float4 v = row[t + 256 * i];
            acc_de[i].x += v.x; acc_de[i].y += v.y;
            acc_de[i].z += v.z; acc_de[i].w += v.w;
            rs += (v.x + v.y) + (v.z + v.w);
        }
#pragma unroll
        for (int o = 16; o; o >>= 1) rs += __shfl_down_sync(0xffffffffu, rs, o);
        if (lane == 0) s_wpart[r][wid] = rs;
    }
    __syncthreads();
    if (t < 128) {
        float s = 0.f;
#pragma unroll
        for (int w = 0; w < 8; ++w) s += s_wpart[t][w];
        g_dv[r0 + t] = s;
        s_dv[t] = s;
    }
    __syncthreads();
    // X1 = d_v * X for this row block
    for (int idx = t; idx < 128 * DF; idx += 256) {
        int r = idx >> 6, f = idx & 63;
        g_X1[(size_t)(r0 + r) * DF + f] = s_dv[r] * X[(size_t)(r0 + r) * DF + f];
    }
    // zero this block's slice of Y (consumed by gemm1 atomics later in stream order)
    {
        const int base = blockIdx.x * ((NE * DF) / 128);  // 4096 per block
        for (int idx = t; idx < (NE * DF) / 128; idx += 256) g_Y[base + idx] = 0.f;
    }
    // d_e partial sums (each thread owns fixed columns within this block)
#pragma unroll
    for (int i = 0; i < 8; ++i) {
        int e = 4 * (t + 256 * i);
        atomicAdd(&g_de[e + 0], acc_de[i].x);
        atomicAdd(&g_de[e + 1], acc_de[i].y);
        atomicAdd(&g_de[e + 2], acc_de[i].z);
        atomicAdd(&g_de[e + 3], acc_de[i].w);
    }
}

// ---------------- kernel 2: Y += H^T @ X1   (tile 128e x 64f, K split 2) ----------------
__global__ __launch_bounds__(256) void k_gemm1(const float* __restrict__ H) {
    constexpr int PA = 136;  // 136 % 32 == 8 -> conflict-free frag loads
    constexpr int PB = 72;   //  72 % 32 == 8
    constexpr int KC = 16;
    constexpr int NCH = 512; // 8192 / 16 per K half

    __shared__ float As[2][KC * PA];  // [k][e]
    __shared__ float Bs[2][KC * PB];  // [k][f]

    const int t = threadIdx.x;
    const int e0 = blockIdx.x * 128;
    const size_t kbase0 = (size_t)blockIdx.y * 8192;
    const int warp = t >> 5, lane = t & 31, g = lane >> 2, t4 = lane & 3;
    const int wm = (warp >> 1) * 32, wn = (warp & 1) * 32;

    float acc[2][4][4];
#pragma unroll
    for (int a = 0; a < 2; ++a)
#pragma unroll
        for (int b = 0; b < 4; ++b)
#pragma unroll
            for (int c = 0; c < 4; ++c) acc[a][b][c] = 0.f;

    auto load_chunk = [&](int ch, int st) {
        const size_t kb = kbase0 + (size_t)ch * KC;
        int idx = t, row = idx >> 5, c4 = idx & 31;
        cp16(smem_u32(&As[st][row * PA + c4 * 4]), H + (kb + row) * NE + e0 + c4 * 4);
        idx = t + 256; row = idx >> 5; c4 = idx & 31;
        cp16(smem_u32(&As[st][row * PA + c4 * 4]), H + (kb + row) * NE + e0 + c4 * 4);
        row = t >> 4; c4 = t & 15;
        cp16(smem_u32(&Bs[st][row * PB + c4 * 4]), g_X1 + (kb + row) * DF + c4 * 4);
    };

    auto compute = [&](int st) {
        const float* A = As[st];
        const float* B = Bs[st];
#pragma unroll
        for (int s = 0; s < 2; ++s) {
            const int k = s * 8 + t4;
            uint32_t ah[2][4], al[2][4], bh[4][2], bl[4][2];
#pragma unroll
            for (int mt = 0; mt < 2; ++mt) {
                int m = wm + mt * 16 + g;
                tf32_split(A[k * PA + m],           ah[mt][0], al[mt][0]);
                tf32_split(A[k * PA + m + 8],       ah[mt][1], al[mt][1]);
                tf32_split(A[(k + 4) * PA + m],     ah[mt][2], al[mt][2]);
                tf32_split(A[(k + 4) * PA + m + 8], ah[mt][3], al[mt][3]);
            }
#pragma unroll
            for (int nt = 0; nt < 4; ++nt) {
                int n = wn + nt * 8 + g;
                tf32_split(B[k * PB + n],       bh[nt][0], bl[nt][0]);
                tf32_split(B[(k + 4) * PB + n], bh[nt][1], bl[nt][1]);
            }
            // 3xTF32: hi*hi + hi*lo + lo*hi (lo*lo term ~2^-22, dropped)
#pragma unroll
            for (int mt = 0; mt < 2; ++mt)
#pragma unroll
                for (int nt = 0; nt < 4; ++nt) mma_tf32(acc[mt][nt], ah[mt], bh[nt]);
#pragma unroll
            for (int mt = 0; mt < 2; ++mt)
#pragma unroll
                for (int nt = 0; nt < 4; ++nt) mma_tf32(acc[mt][nt], ah[mt], bl[nt]);
#pragma unroll
            for (int mt = 0; mt < 2; ++mt)
#pragma unroll
                for (int nt = 0; nt < 4; ++nt) mma_tf32(acc[mt][nt], al[mt], bh[nt]);
        }
    };

    load_chunk(0, 0); cp_commit();
    load_chunk(1, 1); cp_commit();
#pragma unroll 1
    for (int ch = 0; ch < NCH; ++ch) {
        if (ch < NCH - 1) asm volatile("cp.async.wait_group 1;" ::: "memory");
        else              asm volatile("cp.async.wait_group 0;" ::: "memory");
        __syncthreads();
        compute(ch & 1);
        __syncthreads();
        if (ch + 2 < NCH) { load_chunk(ch + 2, ch & 1); cp_commit(); }
    }

    // atomic epilogue (K-split partials)
#pragma unroll
    for (int mt = 0; mt < 2; ++mt) {
        const int e = e0 + wm + mt * 16 + g;
#pragma unroll
        for (int nt = 0; nt < 4; ++nt) {
            const int n = wn + nt * 8 + 2 * t4;
            atomicAdd(&g_Y[(size_t)e * DF + n],           acc[mt][nt][0]);
            atomicAdd(&g_Y[(size_t)e * DF + n + 1],       acc[mt][nt][1]);
            atomicAdd(&g_Y[(size_t)(e + 8) * DF + n],     acc[mt][nt][2]);
            atomicAdd(&g_Y[(size_t)(e + 8) * DF + n + 1], acc[mt][nt][3]);
        }
    }
}

// ---------------- kernel 3: Y *= d_e ----------------
__global__ __launch_bounds__(256) void k_scale_y() {
    const int idx = blockIdx.x * 256 + threadIdx.x;  // over NE*DF/4 f4's
    float4* Y4 = reinterpret_cast<float4*>(g_Y);
    float4 v = Y4[idx];
    const float d = g_de[idx >> 4];
    v.x *= d; v.y *= d; v.z *= d; v.w *= d;
    Y4[idx] = v;
}

// ---------------- kernel 4: out = d_v * (H @ Y) ----------------
__global__ __launch_bounds__(256) void k_gemm2(const float* __restrict__ H,
                                               float* __restrict__ out) {
    constexpr int PA = 20;   // 20*g mod 32 spreads -> conflict-free
    constexpr int PB = 72;
    constexpr int KC = 16;
    constexpr int NCH = 512; // 8192 / 16

    __shared__ float As[2][128 * PA];  // [v][k]
    __shared__ float Bs[2][KC * PB];   // [k][f]

    const int t = threadIdx.x;
    const int v0 = blockIdx.x * 128;
    const int warp = t >> 5, lane = t & 31, g = lane >> 2, t4 = lane & 3;
    const int wm = (warp >> 1) * 32, wn = (warp & 1) * 32;

    float acc[2][4][4];
#pragma unroll
    for (int a = 0; a < 2; ++a)
#pragma unroll
        for (int b = 0; b < 4; ++b)
#pragma unroll
            for (int c = 0; c < 4; ++c) acc[a][b][c] = 0.f;

    auto load_chunk = [&](int ch, int st) {
        const size_t kb = (size_t)ch * KC;
        int idx = t, row = idx >> 2, c4 = idx & 3;
        cp16(smem_u32(&As[st][row * PA + c4 * 4]), H + (size_t)(v0 + row) * NE + kb + c4 * 4);
        idx = t + 256; row = idx >> 2; c4 = idx & 3;
        cp16(smem_u32(&As[st][row * PA + c4 * 4]), H + (size_t)(v0 + row) * NE + kb + c4 * 4);
        row = t >> 4; c4 = t & 15;
        cp16(smem_u32(&Bs[st][row * PB + c4 * 4]), g_Y + (kb + row) * DF + c4 * 4);
    };

    auto compute = [&](int st) {
        const float* A = As[st];
        const float* B = Bs[st];
#pragma unroll
        for (int s = 0; s < 2; ++s) {
            const int k = s * 8 + t4;
            uint32_t ah[2][4], al[2][4], bh[4][2], bl[4][2];
#pragma unroll
            for (int mt = 0; mt < 2; ++mt) {
                int m = wm + mt * 16 + g;
                tf32_split(A[m * PA + k],           ah[mt][0], al[mt][0]);
                tf32_split(A[(m + 8) * PA + k],     ah[mt][1], al[mt][1]);
                tf32_split(A[m * PA + k + 4],       ah[mt][2], al[mt][2]);
                tf32_split(A[(m + 8) * PA + k + 4], ah[mt][3], al[mt][3]);
            }
#pragma unroll
            for (int nt = 0; nt < 4; ++nt) {
                int n = wn + nt * 8 + g;
                tf32_split(B[k * PB + n],       bh[nt][0], bl[nt][0]);
                tf32_split(B[(k + 4) * PB + n], bh[nt][1], bl[nt][1]);
            }
#pragma unroll
            for (int mt = 0; mt < 2; ++mt)
#pragma unroll
                for (int nt = 0; nt < 4; ++nt) mma_tf32(acc[mt][nt], ah[mt], bh[nt]);
#pragma unroll
            for (int mt = 0; mt < 2; ++mt)
#pragma unroll
                for (int nt = 0; nt < 4; ++nt) mma_tf32(acc[mt][nt], ah[mt], bl[nt]);
#pragma unroll
            for (int mt = 0; mt < 2; ++mt)
#pragma unroll
                for (int nt = 0; nt < 4; ++nt) mma_tf32(acc[mt][nt], al[mt], bh[nt]);
        }
    };

    load_chunk(0, 0); cp_commit();
    load_chunk(1, 1); cp_commit();
#pragma unroll 1
    for (int ch = 0; ch < NCH; ++ch) {
        if (ch < NCH - 1) asm volatile("cp.async.wait_group 1;" ::: "memory");
        else              asm volatile("cp.async.wait_group 0;" ::: "memory");
        __syncthreads();
        compute(ch & 1);
        __syncthreads();
        if (ch + 2 < NCH) { load_chunk(ch + 2, ch & 1); cp_commit(); }
    }

    // direct store epilogue with d_v scaling
#pragma unroll
    for (int mt = 0; mt < 2; ++mt) {
        const int v = v0 + wm + mt * 16 + g;
        const float dlo = g_dv[v];
        const float dhi = g_dv[v + 8];
#pragma unroll
        for (int nt = 0; nt < 4; ++nt) {
            const int n = wn + nt * 8 + 2 * t4;
            float2 lo = make_float2(dlo * acc[mt][nt][0], dlo * acc[mt][nt][1]);
            float2 hi = make_float2(dhi * acc[mt][nt][2], dhi * acc[mt][nt][3]);
            *reinterpret_cast<float2*>(&out[(size_t)v * DF + n]) = lo;
            *reinterpret_cast<float2*>(&out[(size_t)(v + 8) * DF + n]) = hi;
        }
    }
}

// ---------------- launch ----------------
extern "C" void kernel_launch(void* const* d_in, const int* in_sizes, int n_in,
                              void* d_out, int out_size) {
    const float* H = (const float*)d_in[0];
    const float* X = (const float*)d_in[1];
    float* out = (float*)d_out;

    void* de_ptr = nullptr;
    cudaGetSymbolAddress(&de_ptr, g_de);
    cudaMemsetAsync(de_ptr, 0, NE * sizeof(float));

    k_deg<<<128, 256>>>(H, X);
    dim3 grid1(NE / 128, 2);
    k_gemm1<<<grid1, 256>>>(H);
    k_scale_y<<<(NE * DF / 4) / 256, 256>>>();
    k_gemm2<<<NN / 128, 256>>>(H, out);
}